// round 7
// baseline (speedup 1.0000x reference)
#include <cuda_runtime.h>

#define BATCH   8192
#define ROW_LEN 128
#define DIM     128

__device__ float g_partials[BATCH];

__global__ __launch_bounds__(128, 10)
void node2vec_row_kernel(const void* __restrict__ rt_raw,
                         const float* __restrict__ X,
                         const int* __restrict__ m_ptr) {
    const int b    = blockIdx.x;
    const int tid  = threadIdx.x;   // 0..127
    const int lane = tid & 31;
    const int warp = tid >> 5;      // 0..3

    __shared__ int   idx_s[ROW_LEN];
    __shared__ float x0s[DIM];
    __shared__ float scores[ROW_LEN];

    const int* __restrict__ rt32 = (const int*)rt_raw;

    // Runtime dtype detection: int64 (<2^31 values) => odd 32-bit words zero.
    const bool is64 = (rt32[1] == 0) & (rt32[3] == 0) & (rt32[5] == 0) & (rt32[7] == 0);

    const long long base = (long long)b * ROW_LEN;

    // Preload this row's 128 indices into shared (one coalesced pass).
    idx_s[tid] = is64 ? rt32[2 * (base + tid)] : rt32[base + tid];

    // x0 = X[rt[b,0]]
    {
        const long long e0 = is64 ? (long long)rt32[2 * base] : (long long)rt32[base];
        x0s[tid] = __ldg(X + e0 * DIM + tid);
    }
    __syncthreads();

    // Each lane holds x0 as two float2 chunks: elements {2*lane, 2*lane+1}
    // and {64+2*lane, 64+2*lane+1}.
    const float2* __restrict__ x02 = reinterpret_cast<const float2*>(x0s);
    const float2 x0a = x02[lane];
    const float2 x0b = x02[lane + 32];

    // Warp w handles rows w*32 .. w*32+31, 4 rows per iteration.
    // Each gather row = 2x LDG.64 (32 lanes x 8B = 256B = 2 lines each):
    // halves LSU issue cost vs LDG.32 while keeping L1tex replays low.
    const int row0 = warp * 32;
    #pragma unroll
    for (int it = 0; it < 8; ++it) {
        const int l = row0 + it * 4;
        const long long i0 = idx_s[l + 0];
        const long long i1 = idx_s[l + 1];
        const long long i2 = idx_s[l + 2];
        const long long i3 = idx_s[l + 3];
        const float2* __restrict__ r0 = reinterpret_cast<const float2*>(X + i0 * DIM) + lane;
        const float2* __restrict__ r1 = reinterpret_cast<const float2*>(X + i1 * DIM) + lane;
        const float2* __restrict__ r2 = reinterpret_cast<const float2*>(X + i2 * DIM) + lane;
        const float2* __restrict__ r3 = reinterpret_cast<const float2*>(X + i3 * DIM) + lane;

        // 8 independent LDG.64 (MLP=8).
        const float2 a0 = __ldg(r0), a1 = __ldg(r0 + 32);
        const float2 b0 = __ldg(r1), b1 = __ldg(r1 + 32);
        const float2 c0 = __ldg(r2), c1 = __ldg(r2 + 32);
        const float2 e0 = __ldg(r3), e1 = __ldg(r3 + 32);

        float d0 = a0.x * x0a.x + a0.y * x0a.y + a1.x * x0b.x + a1.y * x0b.y;
        float d1 = b0.x * x0a.x + b0.y * x0a.y + b1.x * x0b.x + b1.y * x0b.y;
        float d2 = c0.x * x0a.x + c0.y * x0a.y + c1.x * x0b.x + c1.y * x0b.y;
        float d3 = e0.x * x0a.x + e0.y * x0a.y + e1.x * x0b.x + e1.y * x0b.y;

        // Multi-row butterfly: 5 shfls reduce all 4 accumulators.
        float loA = (lane & 16) ? d1 : d0;
        float hiA = (lane & 16) ? d0 : d1;
        loA += __shfl_xor_sync(0xffffffffu, hiA, 16);
        float loB = (lane & 16) ? d3 : d2;
        float hiB = (lane & 16) ? d2 : d3;
        loB += __shfl_xor_sync(0xffffffffu, hiB, 16);
        float lo = (lane & 8) ? loB : loA;
        float hi = (lane & 8) ? loA : loB;
        lo += __shfl_xor_sync(0xffffffffu, hi, 8);
        #pragma unroll
        for (int off = 4; off > 0; off >>= 1)
            lo += __shfl_xor_sync(0xffffffffu, lo, off);

        // lane 0 -> row l+0, lane 8 -> l+2, lane 16 -> l+1, lane 24 -> l+3.
        if ((lane & 7) == 0) {
            const int g = lane >> 3;               // 0..3
            const int sel = (g & 1) * 2 + (g >> 1); // {0,2,1,3}
            scores[l + sel] = lo;
        }
    }
    __syncthreads();

    // Warp 0: softmax stats over 128 scores via shuffles.
    if (warp == 0) {
        const int m = m_ptr[0];     // low 32 bits of int32/int64 LE
        const float s0 = scores[lane];
        const float s1 = scores[lane + 32];
        const float s2 = scores[lane + 64];
        const float s3 = scores[lane + 96];

        float mx = fmaxf(fmaxf(s0, s1), fmaxf(s2, s3));
        #pragma unroll
        for (int off = 16; off > 0; off >>= 1)
            mx = fmaxf(mx, __shfl_xor_sync(0xffffffffu, mx, off));

        float e = __expf(s0 - mx) + __expf(s1 - mx) + __expf(s2 - mx) + __expf(s3 - mx);
        float p = 0.0f;
        if (lane >= 1 && lane <= m)        p += s0;
        if (lane + 32 <= m)                p += s1;
        if (lane + 64 <= m)                p += s2;
        if (lane + 96 <= m)                p += s3;
        #pragma unroll
        for (int off = 16; off > 0; off >>= 1) {
            e += __shfl_xor_sync(0xffffffffu, e, off);
            p += __shfl_xor_sync(0xffffffffu, p, off);
        }

        if (lane == 0) {
            const float lse = mx + __logf(e);
            g_partials[b] = (float)m * lse - p;
        }
    }
}

__global__ __launch_bounds__(1024)
void node2vec_reduce_kernel(float* __restrict__ out) {
    __shared__ float wred[32];
    const int tid  = threadIdx.x;
    const int lane = tid & 31;
    const int warp = tid >> 5;
    const float4* __restrict__ p4 = reinterpret_cast<const float4*>(g_partials);
    const float4 a = p4[tid];
    const float4 c = p4[tid + 1024];
    float s = (a.x + a.y) + (a.z + a.w) + (c.x + c.y) + (c.z + c.w);
    #pragma unroll
    for (int off = 16; off > 0; off >>= 1)
        s += __shfl_xor_sync(0xffffffffu, s, off);
    if (lane == 0) wred[warp] = s;
    __syncthreads();
    if (warp == 0) {
        float t = wred[lane];
        #pragma unroll
        for (int off = 16; off > 0; off >>= 1)
            t += __shfl_xor_sync(0xffffffffu, t, off);
        if (lane == 0) out[0] = t * (1.0f / (float)BATCH);
    }
}

extern "C" void kernel_launch(void* const* d_in, const int* in_sizes, int n_in,
                              void* d_out, int out_size) {
    const void*  rt = d_in[0];                 // rt_batch [8192,128] int32 or int64
    const float* X  = (const float*)d_in[1];   // X float32 [100000,128]
    const int*   m  = (const int*)d_in[2];     // m scalar
    float* out = (float*)d_out;

    node2vec_row_kernel<<<BATCH, 128>>>(rt, X, m);
    node2vec_reduce_kernel<<<1, 1024>>>(out);
}

// round 8
// speedup vs baseline: 1.0653x; 1.0653x over previous
#include <cuda_runtime.h>

#define BATCH   8192
#define ROW_LEN 128
#define DIM     128

__device__ float g_partials[BATCH];

__global__ __launch_bounds__(128, 10)
void node2vec_row_kernel(const void* __restrict__ rt_raw,
                         const float* __restrict__ X,
                         const int* __restrict__ m_ptr) {
    const int b    = blockIdx.x;
    const int tid  = threadIdx.x;   // 0..127
    const int lane = tid & 31;
    const int warp = tid >> 5;      // 0..3

    __shared__ int   idx_s[ROW_LEN];
    __shared__ float x0s[DIM];
    __shared__ float scores[ROW_LEN];

    const int* __restrict__ rt32 = (const int*)rt_raw;

    // Runtime dtype detection: int64 (<2^31 values) => odd 32-bit words zero.
    const bool is64 = (rt32[1] == 0) & (rt32[3] == 0) & (rt32[5] == 0) & (rt32[7] == 0);

    const long long base = (long long)b * ROW_LEN;

    // Preload this row's 128 indices into shared (one coalesced pass).
    idx_s[tid] = is64 ? rt32[2 * (base + tid)] : rt32[base + tid];

    // x0 = X[rt[b,0]]
    {
        const long long e0 = is64 ? (long long)rt32[2 * base] : (long long)rt32[base];
        x0s[tid] = __ldg(X + e0 * DIM + tid);
    }
    __syncthreads();

    // Mixed-width layout per row: elements 0..63 as float2 (LDG.64, 2 lines),
    // elements 64..95 and 96..127 as scalar LDG.32 (1 line each).
    const float2* __restrict__ x02 = reinterpret_cast<const float2*>(x0s);
    const float2 x0p  = x02[lane];        // elements {2*lane, 2*lane+1}
    const float  x0c2 = x0s[64 + lane];   // line 2
    const float  x0c3 = x0s[96 + lane];   // line 3

    // Warp w handles rows w*32 .. w*32+31, 4 rows per iteration.
    // Per row: 1x LDG.64 + 2x LDG.32 = 3 LDG covering the 4 compulsory lines.
    const int row0 = warp * 32;
    #pragma unroll
    for (int it = 0; it < 8; ++it) {
        const int l = row0 + it * 4;
        const long long i0 = idx_s[l + 0];
        const long long i1 = idx_s[l + 1];
        const long long i2 = idx_s[l + 2];
        const long long i3 = idx_s[l + 3];
        const float* __restrict__ p0 = X + i0 * DIM;
        const float* __restrict__ p1 = X + i1 * DIM;
        const float* __restrict__ p2 = X + i2 * DIM;
        const float* __restrict__ p3 = X + i3 * DIM;

        // 12 independent LDGs (4x LDG.64 + 8x LDG.32), MLP=12.
        const float2 a01 = __ldg(reinterpret_cast<const float2*>(p0) + lane);
        const float2 b01 = __ldg(reinterpret_cast<const float2*>(p1) + lane);
        const float2 c01 = __ldg(reinterpret_cast<const float2*>(p2) + lane);
        const float2 e01 = __ldg(reinterpret_cast<const float2*>(p3) + lane);
        const float  a2 = __ldg(p0 + 64 + lane), a3 = __ldg(p0 + 96 + lane);
        const float  b2 = __ldg(p1 + 64 + lane), b3 = __ldg(p1 + 96 + lane);
        const float  c2 = __ldg(p2 + 64 + lane), c3 = __ldg(p2 + 96 + lane);
        const float  e2 = __ldg(p3 + 64 + lane), e3 = __ldg(p3 + 96 + lane);

        float d0 = a01.x * x0p.x + a01.y * x0p.y + a2 * x0c2 + a3 * x0c3;
        float d1 = b01.x * x0p.x + b01.y * x0p.y + b2 * x0c2 + b3 * x0c3;
        float d2 = c01.x * x0p.x + c01.y * x0p.y + c2 * x0c2 + c3 * x0c3;
        float d3 = e01.x * x0p.x + e01.y * x0p.y + e2 * x0c2 + e3 * x0c3;

        // Multi-row butterfly: 5 shfls reduce all 4 accumulators.
        float loA = (lane & 16) ? d1 : d0;
        float hiA = (lane & 16) ? d0 : d1;
        loA += __shfl_xor_sync(0xffffffffu, hiA, 16);
        float loB = (lane & 16) ? d3 : d2;
        float hiB = (lane & 16) ? d2 : d3;
        loB += __shfl_xor_sync(0xffffffffu, hiB, 16);
        float lo = (lane & 8) ? loB : loA;
        float hi = (lane & 8) ? loA : loB;
        lo += __shfl_xor_sync(0xffffffffu, hi, 8);
        #pragma unroll
        for (int off = 4; off > 0; off >>= 1)
            lo += __shfl_xor_sync(0xffffffffu, lo, off);

        // lane 0 -> row l+0, lane 8 -> l+2, lane 16 -> l+1, lane 24 -> l+3.
        if ((lane & 7) == 0) {
            const int g = lane >> 3;               // 0..3
            const int sel = (g & 1) * 2 + (g >> 1); // {0,2,1,3}
            scores[l + sel] = lo;
        }
    }
    __syncthreads();

    // Warp 0: softmax stats over 128 scores via shuffles.
    if (warp == 0) {
        const int m = m_ptr[0];     // low 32 bits of int32/int64 LE
        const float s0 = scores[lane];
        const float s1 = scores[lane + 32];
        const float s2 = scores[lane + 64];
        const float s3 = scores[lane + 96];

        float mx = fmaxf(fmaxf(s0, s1), fmaxf(s2, s3));
        #pragma unroll
        for (int off = 16; off > 0; off >>= 1)
            mx = fmaxf(mx, __shfl_xor_sync(0xffffffffu, mx, off));

        float e = __expf(s0 - mx) + __expf(s1 - mx) + __expf(s2 - mx) + __expf(s3 - mx);
        float p = 0.0f;
        if (lane >= 1 && lane <= m)        p += s0;
        if (lane + 32 <= m)                p += s1;
        if (lane + 64 <= m)                p += s2;
        if (lane + 96 <= m)                p += s3;
        #pragma unroll
        for (int off = 16; off > 0; off >>= 1) {
            e += __shfl_xor_sync(0xffffffffu, e, off);
            p += __shfl_xor_sync(0xffffffffu, p, off);
        }

        if (lane == 0) {
            const float lse = mx + __logf(e);
            g_partials[b] = (float)m * lse - p;
        }
    }
}

__global__ __launch_bounds__(1024)
void node2vec_reduce_kernel(float* __restrict__ out) {
    __shared__ float wred[32];
    const int tid  = threadIdx.x;
    const int lane = tid & 31;
    const int warp = tid >> 5;
    const float4* __restrict__ p4 = reinterpret_cast<const float4*>(g_partials);
    const float4 a = p4[tid];
    const float4 c = p4[tid + 1024];
    float s = (a.x + a.y) + (a.z + a.w) + (c.x + c.y) + (c.z + c.w);
    #pragma unroll
    for (int off = 16; off > 0; off >>= 1)
        s += __shfl_xor_sync(0xffffffffu, s, off);
    if (lane == 0) wred[warp] = s;
    __syncthreads();
    if (warp == 0) {
        float t = wred[lane];
        #pragma unroll
        for (int off = 16; off > 0; off >>= 1)
            t += __shfl_xor_sync(0xffffffffu, t, off);
        if (lane == 0) out[0] = t * (1.0f / (float)BATCH);
    }
}

extern "C" void kernel_launch(void* const* d_in, const int* in_sizes, int n_in,
                              void* d_out, int out_size) {
    const void*  rt = d_in[0];                 // rt_batch [8192,128] int32 or int64
    const float* X  = (const float*)d_in[1];   // X float32 [100000,128]
    const int*   m  = (const int*)d_in[2];     // m scalar
    float* out = (float*)d_out;

    node2vec_row_kernel<<<BATCH, 128>>>(rt, X, m);
    node2vec_reduce_kernel<<<1, 1024>>>(out);
}